// round 14
// baseline (speedup 1.0000x reference)
#include <cuda_runtime.h>
#include <cstdint>

#define IN_DIM 10
#define H      100
#define OUT_D  10
#define Ln     5
#define Bn     64
#define Tn     2048
#define M_ROWS (Bn * Tn)          // 131072
#define CCH    64                 // publish/consume chunk (timesteps)
#define NCHUNK (Tn / CCH)         // 32
#define NSM    152                // GB300 SM count (placement modulus)
#define GEMM_RES 41               // residues [0,41) -> gemm role
#define NREC   (Ln * Bn)          // 320 recurrent CTAs (1 chain each)
#define GRID_F 443                // waves over 152: 123 gemm + 320 rec
#define FH     0                  // h-progress flags  [0,320)
#define FXP    (Ln * Bn)          // xp-ready flags    [320,640)
#define NFLAGS (2 * Ln * Bn)      // 640

// [l][b][t][j]
__device__ float g_xp[(size_t)Ln * Bn * Tn * H];
__device__ float g_h [(size_t)Ln * Bn * Tn * H];
__device__ int   g_flags[NFLAGS];   // zero at load; consumers reset for replays

// ---------------- f32x2 helpers ----------------
__device__ __forceinline__ unsigned long long fma2(unsigned long long a,
                                                   unsigned long long b,
                                                   unsigned long long c) {
    unsigned long long d;
    asm("fma.rn.f32x2 %0, %1, %2, %3;" : "=l"(d) : "l"(a), "l"(b), "l"(c));
    return d;
}
__device__ __forceinline__ unsigned long long add2(unsigned long long a,
                                                   unsigned long long b) {
    unsigned long long d;
    asm("add.rn.f32x2 %0, %1, %2;" : "=l"(d) : "l"(a), "l"(b));
    return d;
}
__device__ __forceinline__ unsigned long long pack2(float lo, float hi) {
    unsigned long long d;
    asm("mov.b64 %0, {%1, %2};" : "=l"(d) : "f"(lo), "f"(hi));
    return d;
}
__device__ __forceinline__ void unpack2(unsigned long long a, float& lo, float& hi) {
    asm("mov.b64 {%0, %1}, %2;" : "=f"(lo), "=f"(hi) : "l"(a));
}
__device__ __forceinline__ int acq_load(const int* p) {
    int v;
    asm volatile("ld.global.acquire.gpu.b32 %0, [%1];" : "=r"(v) : "l"(p) : "memory");
    return v;
}
// L2-coherent load (bypass L1): data written concurrently by other CTAs.
__device__ __forceinline__ float ldcg(const float* p) {
    float v;
    asm volatile("ld.global.cg.f32 %0, [%1];" : "=f"(v) : "l"(p) : "memory");
    return v;
}

// ---------------- single fused kernel: SM-segregated roles ----------------
#define SM_WO 0        // u64[100][2][26]  staged Wih (pair-major, padded)
#define SM_HB 41600    // float[64][101]   staged h chunk
#define SM_BS 67456    // u64[50]          bias pairs
#define SM_SZ 68096

__global__ void __launch_bounds__(128, 3) fused_kernel(
    const float* __restrict__ x,     // [Bn][Tn][IN_DIM]
    const float* __restrict__ Wih0,  // [H][IN_DIM]
    const float* __restrict__ Wih,   // [4][H][H]
    const float* __restrict__ Whh,   // [5][H][H]
    const float* __restrict__ bih,   // [5][H]
    const float* __restrict__ bhh,   // [5][H]
    const float* __restrict__ h0,    // [5][Bn][H]
    const float* __restrict__ Wout,  // [OUT_D][H]
    const float* __restrict__ bout,  // [OUT_D]
    float* __restrict__ y,           // [Bn][Tn][OUT_D]
    float* __restrict__ hf)          // [5][Bn][H]
{
    extern __shared__ __align__(16) unsigned char smraw[];
    const int tid  = threadIdx.x;
    const int bid  = blockIdx.x;
    const int wave = bid / NSM;          // 0..2
    const int sres = bid % NSM;          // SM residue (classic LUT placement)

    if (sres < GEMM_RES) {
        // ======================= GEMM CTA (dedicated SMs) =======================
        const int gid = wave * GEMM_RES + sres;   // 0..122
        unsigned long long* Wo  = (unsigned long long*)(smraw + SM_WO);
        float*              hb  = (float*)(smraw + SM_HB);
        unsigned long long* bsm = (unsigned long long*)(smraw + SM_BS);
        const int row  = tid & 63;
        const int half = tid >> 6;

        // ---------- Phase 1 (gid < 64): xp0 for batch b0 = gid ----------
        if (gid < Bn) {
            const int b0 = gid;
            for (int idx = tid; idx < IN_DIM * 50; idx += 128) {
                int k = idx % IN_DIM, m = idx / IN_DIM;
                int hh = m / 25, i = m - hh * 25;
                Wo[k * 52 + hh * 26 + i] =
                    pack2(Wih0[(2 * m) * IN_DIM + k], Wih0[(2 * m + 1) * IN_DIM + k]);
            }
            for (int m = tid; m < 50; m += 128)
                bsm[m] = pack2(bih[2 * m] + bhh[2 * m], bih[2 * m + 1] + bhh[2 * m + 1]);
            __syncthreads();

            for (int c = 0; c < NCHUNK; c++) {
                const float* xr = x + ((size_t)b0 * Tn + (size_t)c * CCH + row) * IN_DIM;
                float xv[IN_DIM];
#pragma unroll
                for (int k = 0; k < IN_DIM; k++) xv[k] = xr[k];
                unsigned long long acc[25];
#pragma unroll
                for (int i = 0; i < 25; i++) acc[i] = bsm[half * 25 + i];
#pragma unroll
                for (int k = 0; k < IN_DIM; k++) {
                    unsigned long long xkk = pack2(xv[k], xv[k]);
                    const unsigned long long* Wk = Wo + k * 52 + half * 26;
#pragma unroll
                    for (int i = 0; i < 25; i++) acc[i] = fma2(xkk, Wk[i], acc[i]);
                }
                unsigned long long* dst = (unsigned long long*)
                    (g_xp + ((size_t)b0 * Tn + (size_t)c * CCH + row) * H + half * 50);
#pragma unroll
                for (int i = 0; i < 25; i++) dst[i] = acc[i];
                __syncthreads();
                if (tid == 0) {
                    __threadfence();
                    *(volatile int*)&g_flags[FXP + b0] = (c + 1) * CCH;
                }
                __syncthreads();
            }
            __syncthreads();
        }

        // ---------- Phase 2: layer-l input transform ----------
        // gid: [0,30) -> l=1 (30 CTAs, stride 30); [30,61) l=2; [61,92) l=3; [92,123) l=4.
        int l, r, nb, stride;
        if (gid < 30)      { l = 1; r = gid;      stride = 30; nb = (r < 4) ? 3 : 2; }
        else if (gid < 61) { l = 2; r = gid - 30; stride = 31; nb = (r < 2) ? 3 : 2; }
        else if (gid < 92) { l = 3; r = gid - 61; stride = 31; nb = (r < 2) ? 3 : 2; }
        else               { l = 4; r = gid - 92; stride = 31; nb = (r < 2) ? 3 : 2; }

        const float* W = Wih + (size_t)(l - 1) * H * H;
        for (int idx = tid; idx < H * 50; idx += 128) {
            int k = idx % H, m = idx / H;
            int hh = m / 25, i = m - hh * 25;
            Wo[k * 52 + hh * 26 + i] = pack2(W[(2 * m) * H + k], W[(2 * m + 1) * H + k]);
        }
        for (int m = tid; m < 50; m += 128) {
            bsm[m] = pack2(bih[l * H + 2 * m] + bhh[l * H + 2 * m],
                           bih[l * H + 2 * m + 1] + bhh[l * H + 2 * m + 1]);
        }
        __syncthreads();

        for (int c = 0; c < NCHUNK; c++) {
            for (int ib = 0; ib < nb; ib++) {
                const int b = r + stride * ib;
                const int need = (c + 1) * CCH;
                while (acq_load(&g_flags[FH + (l - 1) * Bn + b]) < need) __nanosleep(200);

                const float* src = g_h + (((size_t)(l - 1) * Bn + b) * Tn
                                          + (size_t)c * CCH) * H;
                for (int idx = tid; idx < CCH * H; idx += 128) {
                    int rr = idx / H, k = idx - rr * H;
                    hb[rr * 101 + k] = ldcg(src + idx);
                }
                __syncthreads();

                unsigned long long acc[25];
#pragma unroll
                for (int i = 0; i < 25; i++) acc[i] = bsm[half * 25 + i];
                const float* hrow = hb + row * 101;
#pragma unroll 2
                for (int k = 0; k < H; k++) {
                    float xk = hrow[k];
                    unsigned long long xkk = pack2(xk, xk);
                    const unsigned long long* Wk = Wo + k * 52 + half * 26;
#pragma unroll
                    for (int i = 0; i < 25; i++) acc[i] = fma2(xkk, Wk[i], acc[i]);
                }
                unsigned long long* dst = (unsigned long long*)
                    (g_xp + (((size_t)l * Bn + b) * Tn + (size_t)c * CCH + row) * H
                     + half * 50);
#pragma unroll
                for (int i = 0; i < 25; i++) dst[i] = acc[i];
                __syncthreads();
                if (tid == 0) {
                    __threadfence();
                    *(volatile int*)&g_flags[FXP + l * Bn + b] = need;
                }
                __syncthreads();
            }
        }
        // Reset the h flags this CTA consumed (for next graph replay).
        if (tid == 0) {
            for (int ib = 0; ib < nb; ib++)
                g_flags[FH + (l - 1) * Bn + (r + stride * ib)] = 0;
        }

        // ---------- Phase 3 (gid < 64): output projection for batch b0 = gid ----------
        if (gid < Bn) {
            const int b0 = gid;
            __syncthreads();
            for (int idx = tid; idx < H * 5; idx += 128) {
                int k = idx % H, i = idx / H;
                Wo[k * 6 + i] = pack2(Wout[(2 * i) * H + k], Wout[(2 * i + 1) * H + k]);
            }
            if (tid < 5) bsm[tid] = pack2(bout[2 * tid], bout[2 * tid + 1]);
            __syncthreads();

            const int* pf = &g_flags[FH + 4 * Bn + b0];
            for (int c = 0; c < NCHUNK; c++) {
                while (acq_load(pf) < (c + 1) * CCH) __nanosleep(200);
                const float* src = g_h + (((size_t)4 * Bn + b0) * Tn + (size_t)c * CCH) * H;
                for (int idx = tid; idx < CCH * H; idx += 128) {
                    int rr = idx / H, k = idx - rr * H;
                    hb[rr * 101 + k] = ldcg(src + idx);
                }
                __syncthreads();
                if (tid < CCH) {
                    unsigned long long acc[5];
#pragma unroll
                    for (int i = 0; i < 5; i++) acc[i] = bsm[i];
                    const float* hrow = hb + tid * 101;
#pragma unroll 4
                    for (int k = 0; k < H; k++) {
                        float hk = hrow[k];
                        unsigned long long xkk = pack2(hk, hk);
                        const unsigned long long* Wk = Wo + k * 6;
#pragma unroll
                        for (int i = 0; i < 5; i++) acc[i] = fma2(xkk, Wk[i], acc[i]);
                    }
                    unsigned long long* yr = (unsigned long long*)
                        (y + ((size_t)b0 * Tn + (size_t)c * CCH + tid) * OUT_D);
#pragma unroll
                    for (int i = 0; i < 5; i++) yr[i] = acc[i];
                }
                __syncthreads();
            }
            if (tid == 0) g_flags[FH + 4 * Bn + b0] = 0;   // consumer reset
        }
        return;
    }

    // ======================= RECURRENT CTA (dedicated SMs) =======================
    const int rid = wave * (NSM - GEMM_RES) + (sres - GEMM_RES);   // 0..319
    if (rid >= NREC) return;
    const int l = rid >> 6;
    const int b = rid & 63;
    const int j = tid;

    float* hs0 = (float*)smraw;              // [104]
    float* hs1 = hs0 + 104;

    unsigned long long w[50];
    if (j < H) {
        const unsigned long long* wr =
            (const unsigned long long*)(Whh + ((size_t)l * H + j) * H);
#pragma unroll
        for (int i = 0; i < 50; i++) w[i] = wr[i];
        hs0[j] = h0[((size_t)l * Bn + b) * H + j];
    }
    __syncthreads();

    const float* xp = g_xp + ((size_t)l * Bn + b) * Tn * H;
    float* hout = g_h + ((size_t)l * Bn + b) * Tn * H;
    const int* srcflag = &g_flags[FXP + l * Bn + b];
    volatile int* pubflag = (volatile int*)&g_flags[FH + l * Bn + b];  // l=4 -> proj

    int seen = 0;
    while (seen < 1) seen = acq_load(srcflag);
    float xv = (j < H) ? ldcg(xp + j) : 0.f;

#pragma unroll 1
    for (int t = 0; t < Tn; t++) {
        float xnext = 0.f;
        if (t + 1 < Tn) {
            while (seen < t + 2) seen = acq_load(srcflag);   // jumps by CCH: rare
            if (j < H) xnext = ldcg(xp + (size_t)(t + 1) * H + j);
        }
        const int p = t & 1;
        if (j < H) {
            const ulonglong2* hp = (const ulonglong2*)(p ? hs1 : hs0);
            unsigned long long a0 = 0ull, a1 = 0ull, a2 = 0ull, a3 = 0ull;
#pragma unroll
            for (int g = 0; g < 5; g++) {        // 5 groups of 5: <=5 hv live
#pragma unroll
                for (int q = 0; q < 5; q++) {
                    const int i = g * 5 + q;
                    ulonglong2 hv = hp[i];
                    if (i & 1) {
                        a2 = fma2(w[2 * i],     hv.x, a2);
                        a3 = fma2(w[2 * i + 1], hv.y, a3);
                    } else {
                        a0 = fma2(w[2 * i],     hv.x, a0);
                        a1 = fma2(w[2 * i + 1], hv.y, a1);
                    }
                }
                asm volatile("" ::: "memory");
            }
            unsigned long long s2 = add2(add2(a0, a2), add2(a1, a3));
            float slo, shi;
            unpack2(s2, slo, shi);
            float s = slo + shi + xv;
            float e  = __expf(2.0f * s);
            float th = 1.0f - __fdividef(2.0f, e + 1.0f);
            (p ? hs0 : hs1)[j] = th;
            hout[(size_t)t * H + j] = th;
        }
        __syncthreads();
        if (((t + 1) & (CCH - 1)) == 0 && tid == 0) {
            __threadfence();
            *pubflag = t + 1;
        }
        xv = xnext;
    }

    if (j < H) hf[((size_t)l * Bn + b) * H + j] = hs0[j];   // Tn even -> hs0
    if (tid == 0) g_flags[FXP + l * Bn + b] = 0;             // consumer reset
}

// ---------------- launcher: ONE kernel ----------------
extern "C" void kernel_launch(void* const* d_in, const int* in_sizes, int n_in,
                              void* d_out, int out_size)
{
    const float* x    = (const float*)d_in[0];
    const float* h0   = (const float*)d_in[1];
    const float* Wih0 = (const float*)d_in[2];
    const float* Wih  = (const float*)d_in[3];
    const float* Whh  = (const float*)d_in[4];
    const float* bih  = (const float*)d_in[5];
    const float* bhh  = (const float*)d_in[6];
    const float* Wout = (const float*)d_in[7];
    const float* bout = (const float*)d_in[8];

    float* y  = (float*)d_out;                        // [B,T,OUT]
    float* hf = y + (size_t)Bn * Tn * OUT_D;          // [L,B,H]

    cudaFuncSetAttribute(fused_kernel, cudaFuncAttributeMaxDynamicSharedMemorySize, SM_SZ);

    fused_kernel<<<GRID_F, 128, SM_SZ>>>(x, Wih0, Wih, Whh, bih, bhh, h0,
                                         Wout, bout, y, hf);
}